// round 5
// baseline (speedup 1.0000x reference)
#include <cuda_runtime.h>
#include <math.h>
#include <stdint.h>

#define BB 2
#define SS 2048
#define DD 1024
#define HH 16
#define DH 64
#define MM (BB*SS)          // 4096
#define SCALE 0.125f        // dh^-0.5

#define LDQ 68              // tf32 tile row stride (64 cols + pad)
#define LDW 132             // wide row stride (128 cols + pad)

// ------------------------------ scratch ------------------------------------
__device__ float g_xn[MM*DD];
__device__ float g_q [MM*DD];
__device__ float g_k [MM*DD];
__device__ float g_v [MM*DD];
__device__ float g_pe[SS*DD];
__device__ float g_p [SS*DD];
__device__ float g_head[MM*DD];
__device__ float g_wt[5*DD*DD];                   // transposed Wq,Wk,Wv,Wp,Wo
__device__ float g_vt[(size_t)BB*HH*DH*SS];       // per-head transposed V

// ------------------------------ helpers ------------------------------------
__device__ __forceinline__ uint32_t f2tf(float f) {
    uint32_t u;
    asm("cvt.rna.tf32.f32 %0, %1;" : "=r"(u) : "f"(f));
    return u;
}

__device__ __forceinline__ void mma8(float* c, const uint32_t* a, const uint32_t* b) {
    asm volatile(
        "mma.sync.aligned.m16n8k8.row.col.f32.tf32.tf32.f32 "
        "{%0,%1,%2,%3}, {%4,%5,%6,%7}, {%8,%9}, {%0,%1,%2,%3};"
        : "+f"(c[0]), "+f"(c[1]), "+f"(c[2]), "+f"(c[3])
        : "r"(a[0]), "r"(a[1]), "r"(a[2]), "r"(a[3]), "r"(b[0]), "r"(b[1]));
}

// --------------------- generic nt tf32 GEMM core ---------------------------
template<int BM, int BN>
__device__ __forceinline__ void gemm_nt_core(
    const float* __restrict__ A, int lda,
    const float* __restrict__ Bt, int ldb,
    float* __restrict__ C, int ldc,
    int K,
    const float* __restrict__ abias,
    const float* __restrict__ cbias)
{
    constexpr int WNB = BN / 32;
    __shared__ __align__(16) uint32_t As[BM][36];
    __shared__ __align__(16) uint32_t Bs[BN][36];

    const int t = threadIdx.x;
    const int wid = t >> 5, lane = t & 31;
    const int wm = wid / WNB, wn = wid % WNB;
    const int lr = lane >> 2, lc = lane & 3;

    float acc[4][4][4];
#pragma unroll
    for (int mf = 0; mf < 4; mf++)
#pragma unroll
        for (int nf = 0; nf < 4; nf++)
#pragma unroll
            for (int r = 0; r < 4; r++) acc[mf][nf][r] = 0.f;

    const int arow = t >> 3;
    const int ac4  = (t & 7) << 2;

    for (int k0 = 0; k0 < K; k0 += 32) {
        __syncthreads();
#pragma unroll
        for (int it = 0; it < BM/32; it++) {
            int r = arow + it*32;
            float4 v4 = *(const float4*)(A + (size_t)r*lda + k0 + ac4);
            if (abias) {
                v4.x += abias[k0+ac4+0]; v4.y += abias[k0+ac4+1];
                v4.z += abias[k0+ac4+2]; v4.w += abias[k0+ac4+3];
            }
            uint4 u = make_uint4(f2tf(v4.x), f2tf(v4.y), f2tf(v4.z), f2tf(v4.w));
            *(uint4*)&As[r][ac4] = u;
        }
#pragma unroll
        for (int it = 0; it < BN/32; it++) {
            int r = arow + it*32;
            float4 v4 = *(const float4*)(Bt + (size_t)r*ldb + k0 + ac4);
            uint4 u = make_uint4(f2tf(v4.x), f2tf(v4.y), f2tf(v4.z), f2tf(v4.w));
            *(uint4*)&Bs[r][ac4] = u;
        }
        __syncthreads();

#pragma unroll
        for (int kk = 0; kk < 4; kk++) {
            const int kb = kk * 8;
            uint32_t a[4][4], b[4][2];
#pragma unroll
            for (int mf = 0; mf < 4; mf++) {
                int m = wm*64 + mf*16;
                a[mf][0] = As[m+lr  ][kb+lc  ];
                a[mf][1] = As[m+lr+8][kb+lc  ];
                a[mf][2] = As[m+lr  ][kb+lc+4];
                a[mf][3] = As[m+lr+8][kb+lc+4];
            }
#pragma unroll
            for (int nf = 0; nf < 4; nf++) {
                int n = wn*32 + nf*8;
                b[nf][0] = Bs[n+lr][kb+lc  ];
                b[nf][1] = Bs[n+lr][kb+lc+4];
            }
#pragma unroll
            for (int mf = 0; mf < 4; mf++)
#pragma unroll
                for (int nf = 0; nf < 4; nf++)
                    mma8(acc[mf][nf], a[mf], b[nf]);
        }
    }

#pragma unroll
    for (int mf = 0; mf < 4; mf++) {
        int m = wm*64 + mf*16;
#pragma unroll
        for (int nf = 0; nf < 4; nf++) {
            int n = wn*32 + nf*8 + 2*lc;
            float b0 = cbias ? cbias[n]   : 0.f;
            float b1 = cbias ? cbias[n+1] : 0.f;
            *(float2*)(C + (size_t)(m+lr  )*ldc + n) =
                make_float2(acc[mf][nf][0] + b0, acc[mf][nf][1] + b1);
            *(float2*)(C + (size_t)(m+lr+8)*ldc + n) =
                make_float2(acc[mf][nf][2] + b0, acc[mf][nf][3] + b1);
        }
    }
}

__global__ void __launch_bounds__(256) proj_tc(
    const float* __restrict__ A, const float* __restrict__ Bt,
    const float* __restrict__ cbias, float* __restrict__ C)
{
    const float* Ab  = A  + (size_t)blockIdx.y * 128 * DD;
    const float* Btb = Bt + (size_t)blockIdx.x * 128 * DD;
    float* Cb = C + (size_t)blockIdx.y * 128 * DD + blockIdx.x * 128;
    gemm_nt_core<128,128>(Ab, DD, Btb, DD, Cb, DD, DD, nullptr,
                          cbias ? cbias + blockIdx.x*128 : nullptr);
}

// =================== fused flash attention with relative shift ==============
// grid (16 i-tiles, 32 bh), 256 threads = 8 warps (warp = 16 query rows).
extern __shared__ char smx[];

__global__ void __launch_bounds__(256, 1) flash_tc(
    const float* __restrict__ q, const float* __restrict__ k,
    const float* __restrict__ vt, const float* __restrict__ p,
    const float* __restrict__ u_bias, const float* __restrict__ v_bias,
    float* __restrict__ head)
{
    uint32_t* Qu  = (uint32_t*)smx;              // [128][LDQ] tf32, q+u
    uint32_t* Qv  = Qu + 128*LDQ;                // [144][LDQ] tf32, q+v (row 128 = q[i0+128])
    uint32_t* Buf = Qv + 144*LDQ;                // [128][LDQ] (K/pg) or [64][LDW] (Vt)
    float*    Gb  = (float*)(Buf + 128*LDQ);     // [144][LDW] fp32 G, or [128][LDW] tf32 P
    uint32_t* Pb  = (uint32_t*)Gb;

    const int z = blockIdx.y, b = z >> 4, h = z & 15;
    const int i0 = blockIdx.x * 128;
    const int t = threadIdx.x, wid = t >> 5, lane = t & 31;
    const int lr = lane >> 2, lc = lane & 3;
    const int mw = wid * 16;

    const float* qb  = q + (size_t)(b*SS)*DD + h*DH;
    const float* kbp = k + (size_t)(b*SS)*DD + h*DH;
    const float* pbp = p + h*DH;
    const float* vtb = vt + (size_t)z*DH*SS;
    const float* ub  = u_bias + h*DH;
    const float* vb  = v_bias + h*DH;

    // load Qu (q+u, 128 rows) and Qv (q+v, 129 rows; 129..143 zero)
    for (int idx = t; idx < 144*16; idx += 256) {
        int row = idx >> 4;
        int c4  = (idx & 15) << 2;
        if (row < 128) {
            float4 v4 = *(const float4*)(qb + (size_t)(i0+row)*DD + c4);
            *(uint4*)&Qu[row*LDQ + c4] = make_uint4(
                f2tf(v4.x+ub[c4]), f2tf(v4.y+ub[c4+1]),
                f2tf(v4.z+ub[c4+2]), f2tf(v4.w+ub[c4+3]));
            *(uint4*)&Qv[row*LDQ + c4] = make_uint4(
                f2tf(v4.x+vb[c4]), f2tf(v4.y+vb[c4+1]),
                f2tf(v4.z+vb[c4+2]), f2tf(v4.w+vb[c4+3]));
        } else if (row == 128) {
            int rs = min(i0+128, SS-1);      // clamped; unused when i0+128==SS
            float4 v4 = *(const float4*)(qb + (size_t)rs*DD + c4);
            *(uint4*)&Qv[row*LDQ + c4] = make_uint4(
                f2tf(v4.x+vb[c4]), f2tf(v4.y+vb[c4+1]),
                f2tf(v4.z+vb[c4+2]), f2tf(v4.w+vb[c4+3]));
        } else {
            *(uint4*)&Qv[row*LDQ + c4] = make_uint4(0,0,0,0);
        }
    }

    float sacc[16][4];
    float oacc[8][4];
    float m0 = -1e30f, m1 = -1e30f, l0 = 0.f, l1 = 0.f;
#pragma unroll
    for (int nf = 0; nf < 8; nf++)
#pragma unroll
        for (int c = 0; c < 4; c++) oacc[nf][c] = 0.f;

    for (int j0 = 0; j0 < SS; j0 += 128) {
        const int R0 = i0 - j0 - 127;
        __syncthreads();   // protect Buf/Pb from previous iteration's readers

        // ---- K tile ----
        for (int idx = t; idx < 128*16; idx += 256) {
            int row = idx >> 4, c4 = (idx & 15) << 2;
            float4 v4 = *(const float4*)(kbp + (size_t)(j0+row)*DD + c4);
            *(uint4*)&Buf[row*LDQ + c4] = make_uint4(
                f2tf(v4.x), f2tf(v4.y), f2tf(v4.z), f2tf(v4.w));
        }
        __syncthreads();

        // ---- content MMA: sacc = (q+u) . k^T ----
#pragma unroll
        for (int nf = 0; nf < 16; nf++)
#pragma unroll
            for (int c = 0; c < 4; c++) sacc[nf][c] = 0.f;
#pragma unroll
        for (int kk = 0; kk < 8; kk++) {
            int kb8 = kk*8;
            uint32_t a[4];
            a[0] = Qu[(mw+lr  )*LDQ + kb8+lc  ];
            a[1] = Qu[(mw+lr+8)*LDQ + kb8+lc  ];
            a[2] = Qu[(mw+lr  )*LDQ + kb8+lc+4];
            a[3] = Qu[(mw+lr+8)*LDQ + kb8+lc+4];
#pragma unroll
            for (int nf = 0; nf < 16; nf++) {
                uint32_t bb[2];
                bb[0] = Buf[(nf*8+lr)*LDQ + kb8+lc  ];
                bb[1] = Buf[(nf*8+lr)*LDQ + kb8+lc+4];
                mma8(sacc[nf], a, bb);
            }
        }
        __syncthreads();

        // ---- positional term via G matrix, two 128-wide r-chunks ----
        for (int half = 0; half < 2; half++) {
            // gather p rows for r = R0 + half*128 + rc
            for (int idx = t; idx < 128*16; idx += 256) {
                int rc = idx >> 4, c4 = (idx & 15) << 2;
                int r = R0 + half*128 + rc;
                int pidx = (r >= 0) ? (SS-1-r) : (-r-1);
                pidx = max(0, min(SS-1, pidx));
                float4 v4 = *(const float4*)(pbp + (size_t)pidx*DD + c4);
                *(uint4*)&Buf[rc*LDQ + c4] = make_uint4(
                    f2tf(v4.x), f2tf(v4.y), f2tf(v4.z), f2tf(v4.w));
            }
            __syncthreads();

            // G = (q+v) . pg^T   (144 rows of m covered by 9 frags)
            for (int f = wid; f < 9; f += 8) {
                int mg = f*16;
#pragma unroll
                for (int nh = 0; nh < 2; nh++) {
                    float gacc[8][4];
#pragma unroll
                    for (int nf = 0; nf < 8; nf++)
#pragma unroll
                        for (int c = 0; c < 4; c++) gacc[nf][c] = 0.f;
#pragma unroll
                    for (int kk = 0; kk < 8; kk++) {
                        int kb8 = kk*8;
                        uint32_t a[4];
                        a[0] = Qv[(mg+lr  )*LDQ + kb8+lc  ];
                        a[1] = Qv[(mg+lr+8)*LDQ + kb8+lc  ];
                        a[2] = Qv[(mg+lr  )*LDQ + kb8+lc+4];
                        a[3] = Qv[(mg+lr+8)*LDQ + kb8+lc+4];
#pragma unroll
                        for (int nf = 0; nf < 8; nf++) {
                            int n = (nh*8+nf)*8;
                            uint32_t bb[2];
                            bb[0] = Buf[(n+lr)*LDQ + kb8+lc  ];
                            bb[1] = Buf[(n+lr)*LDQ + kb8+lc+4];
                            mma8(gacc[nf], a, bb);
                        }
                    }
#pragma unroll
                    for (int nf = 0; nf < 8; nf++) {
                        int n = (nh*8+nf)*8 + 2*lc;
                        Gb[(mg+lr  )*LDW + n  ] = gacc[nf][0];
                        Gb[(mg+lr  )*LDW + n+1] = gacc[nf][1];
                        Gb[(mg+lr+8)*LDW + n  ] = gacc[nf][2];
                        Gb[(mg+lr+8)*LDW + n+1] = gacc[nf][3];
                    }
                }
            }
            __syncthreads();

            // gather shifted pos scores into sacc
            const int ibase = i0 + mw + lr;
#pragma unroll
            for (int nf = 0; nf < 16; nf++) {
#pragma unroll
                for (int c = 0; c < 4; c++) {
                    int i = ibase + ((c >> 1) << 3);
                    int j = j0 + nf*8 + 2*lc + (c & 1);
                    int m_, r_;
                    if (j <= i)          { m_ = i;   r_ = i - j; }
                    else if (j == i + 1) { continue; }
                    else                 { m_ = i+1; r_ = i+1 - j; }
                    int rcg = r_ - R0;
                    if ((rcg >> 7) == half)
                        sacc[nf][c] += Gb[(m_ - i0)*LDW + (rcg & 127)];
                }
            }
            __syncthreads();
        }

        // ---- scale + online softmax ----
        float mx0 = -1e30f, mx1 = -1e30f;
#pragma unroll
        for (int nf = 0; nf < 16; nf++) {
            sacc[nf][0] *= SCALE; sacc[nf][1] *= SCALE;
            sacc[nf][2] *= SCALE; sacc[nf][3] *= SCALE;
            mx0 = fmaxf(mx0, fmaxf(sacc[nf][0], sacc[nf][1]));
            mx1 = fmaxf(mx1, fmaxf(sacc[nf][2], sacc[nf][3]));
        }
        mx0 = fmaxf(mx0, __shfl_xor_sync(0xffffffffu, mx0, 1));
        mx0 = fmaxf(mx0, __shfl_xor_sync(0xffffffffu, mx0, 2));
        mx1 = fmaxf(mx1, __shfl_xor_sync(0xffffffffu, mx1, 1));
        mx1 = fmaxf(mx1, __shfl_xor_sync(0xffffffffu, mx1, 2));
        float nm0 = fmaxf(m0, mx0), nm1 = fmaxf(m1, mx1);
        float f0 = __expf(m0 - nm0), f1 = __expf(m1 - nm1);
        float s0 = 0.f, s1 = 0.f;
#pragma unroll
        for (int nf = 0; nf < 16; nf++) {
            float e0 = __expf(sacc[nf][0] - nm0);
            float e1 = __expf(sacc[nf][1] - nm0);
            float e2 = __expf(sacc[nf][2] - nm1);
            float e3 = __expf(sacc[nf][3] - nm1);
            s0 += e0 + e1; s1 += e2 + e3;
            int n = nf*8 + 2*lc;
            Pb[(mw+lr  )*LDW + n  ] = f2tf(e0);
            Pb[(mw+lr  )*LDW + n+1] = f2tf(e1);
            Pb[(mw+lr+8)*LDW + n  ] = f2tf(e2);
            Pb[(mw+lr+8)*LDW + n+1] = f2tf(e3);
        }
        s0 += __shfl_xor_sync(0xffffffffu, s0, 1);
        s0 += __shfl_xor_sync(0xffffffffu, s0, 2);
        s1 += __shfl_xor_sync(0xffffffffu, s1, 1);
        s1 += __shfl_xor_sync(0xffffffffu, s1, 2);
        l0 = l0*f0 + s0; l1 = l1*f1 + s1;
        m0 = nm0; m1 = nm1;
#pragma unroll
        for (int nf = 0; nf < 8; nf++) {
            oacc[nf][0] *= f0; oacc[nf][1] *= f0;
            oacc[nf][2] *= f1; oacc[nf][3] *= f1;
        }

        // ---- Vt tile ----
        for (int idx = t; idx < 64*32; idx += 256) {
            int d = idx >> 5, c4 = (idx & 31) << 2;
            float4 v4 = *(const float4*)(vtb + (size_t)d*SS + j0 + c4);
            *(uint4*)&Buf[d*LDW + c4] = make_uint4(
                f2tf(v4.x), f2tf(v4.y), f2tf(v4.z), f2tf(v4.w));
        }
        __syncthreads();

        // ---- PV MMA: oacc += P . V ----
#pragma unroll
        for (int kk = 0; kk < 16; kk++) {
            int kb8 = kk*8;
            uint32_t a[4];
            a[0] = Pb[(mw+lr  )*LDW + kb8+lc  ];
            a[1] = Pb[(mw+lr+8)*LDW + kb8+lc  ];
            a[2] = Pb[(mw+lr  )*LDW + kb8+lc+4];
            a[3] = Pb[(mw+lr+8)*LDW + kb8+lc+4];
#pragma unroll
            for (int nf = 0; nf < 8; nf++) {
                uint32_t bb[2];
                bb[0] = Buf[(nf*8+lr)*LDW + kb8+lc  ];
                bb[1] = Buf[(nf*8+lr)*LDW + kb8+lc+4];
                mma8(oacc[nf], a, bb);
            }
        }
    }

    // ---- epilogue ----
    float inv0 = 1.f / l0, inv1 = 1.f / l1;
    float* hb = head + (size_t)(b*SS)*DD + h*DH;
#pragma unroll
    for (int nf = 0; nf < 8; nf++) {
        int n = nf*8 + 2*lc;
        *(float2*)(hb + (size_t)(i0+mw+lr  )*DD + n) =
            make_float2(oacc[nf][0]*inv0, oacc[nf][1]*inv0);
        *(float2*)(hb + (size_t)(i0+mw+lr+8)*DD + n) =
            make_float2(oacc[nf][2]*inv1, oacc[nf][3]*inv1);
    }
}

#define FLASH_SMEM ((128*LDQ + 144*LDQ + 128*LDQ)*4 + 144*LDW*4)

// ------------------------------ transposes ---------------------------------
__global__ void transpose1024(const float* __restrict__ src, float* __restrict__ dst) {
    __shared__ float tile[32][33];
    int bx = blockIdx.x*32, by = blockIdx.y*32;
    int tx = threadIdx.x, ty = threadIdx.y;
#pragma unroll
    for (int r = 0; r < 32; r += 8)
        tile[ty+r][tx] = src[(size_t)(by+ty+r)*DD + bx+tx];
    __syncthreads();
#pragma unroll
    for (int r = 0; r < 32; r += 8)
        dst[(size_t)(bx+ty+r)*DD + by+tx] = tile[tx][ty+r];
}

__global__ void vtrans(const float* __restrict__ v, float* __restrict__ vt) {
    __shared__ float tile[32][33];
    int z = blockIdx.z, b = z >> 4, h = z & 15;
    int s0 = blockIdx.x*32, d0 = blockIdx.y*32;
    int tx = threadIdx.x, ty = threadIdx.y;
#pragma unroll
    for (int r = 0; r < 32; r += 8)
        tile[ty+r][tx] = v[(size_t)(b*SS + s0+ty+r)*DD + h*DH + d0 + tx];
    __syncthreads();
#pragma unroll
    for (int r = 0; r < 32; r += 8)
        vt[(size_t)z*DH*SS + (size_t)(d0+ty+r)*SS + s0+tx] = tile[tx][ty+r];
}

// ------------------------------ LayerNorm ----------------------------------
__global__ void ln_kernel(const float* __restrict__ x,
                          const float* __restrict__ g,
                          const float* __restrict__ b,
                          float* __restrict__ xn) {
    int row = blockIdx.x;
    const float* xr = x + (size_t)row * DD;
    float* outr = xn + (size_t)row * DD;
    int t = threadIdx.x;

    float s = 0.f, s2 = 0.f;
    for (int i = t; i < DD; i += 256) { float v = xr[i]; s += v; s2 += v*v; }

    __shared__ float rs[256], rs2[256];
    rs[t] = s; rs2[t] = s2; __syncthreads();
    for (int off = 128; off > 0; off >>= 1) {
        if (t < off) { rs[t] += rs[t+off]; rs2[t] += rs2[t+off]; }
        __syncthreads();
    }
    float mean = rs[0] * (1.0f/DD);
    float var  = rs2[0] * (1.0f/DD) - mean*mean;
    float inv  = rsqrtf(var + 1e-5f);
    for (int i = t; i < DD; i += 256)
        outr[i] = (xr[i] - mean) * inv * g[i] + b[i];
}

// ------------------------------ sinusoidal PE -------------------------------
__global__ void pe_kernel(float* __restrict__ pe) {
    int idx = blockIdx.x * blockDim.x + threadIdx.x;
    if (idx >= SS * (DD/2)) return;
    int s = idx / (DD/2);
    int i = idx % (DD/2);
    double div = exp(-(double)(2*i) * log(10000.0) / (double)DD);
    double ang = (double)s * div;
    pe[(size_t)s*DD + 2*i    ] = (float)sin(ang);
    pe[(size_t)s*DD + 2*i + 1] = (float)cos(ang);
}

// ------------------------------ launch -------------------------------------
extern "C" void kernel_launch(void* const* d_in, const int* in_sizes, int n_in,
                              void* d_out, int out_size) {
    const float* x    = (const float*)d_in[0];
    const float* ln_g = (const float*)d_in[1];
    const float* ln_b = (const float*)d_in[2];
    const float* Wq   = (const float*)d_in[3];
    const float* bq   = (const float*)d_in[4];
    const float* Wk   = (const float*)d_in[5];
    const float* bk   = (const float*)d_in[6];
    const float* Wv   = (const float*)d_in[7];
    const float* bv   = (const float*)d_in[8];
    const float* Wp   = (const float*)d_in[9];
    const float* Wo   = (const float*)d_in[10];
    const float* bo   = (const float*)d_in[11];
    const float* u_bias = (const float*)d_in[12];
    const float* v_bias = (const float*)d_in[13];
    float* out = (float*)d_out;

    float *xn, *q, *k, *v, *pe, *p, *head, *wt, *vt;
    cudaGetSymbolAddress((void**)&xn, g_xn);
    cudaGetSymbolAddress((void**)&q, g_q);
    cudaGetSymbolAddress((void**)&k, g_k);
    cudaGetSymbolAddress((void**)&v, g_v);
    cudaGetSymbolAddress((void**)&pe, g_pe);
    cudaGetSymbolAddress((void**)&p, g_p);
    cudaGetSymbolAddress((void**)&head, g_head);
    cudaGetSymbolAddress((void**)&wt, g_wt);
    cudaGetSymbolAddress((void**)&vt, g_vt);

    float* wtq = wt + 0*(size_t)DD*DD;
    float* wtk = wt + 1*(size_t)DD*DD;
    float* wtv = wt + 2*(size_t)DD*DD;
    float* wtp = wt + 3*(size_t)DD*DD;
    float* wto = wt + 4*(size_t)DD*DD;

    cudaFuncSetAttribute(flash_tc, cudaFuncAttributeMaxDynamicSharedMemorySize,
                         FLASH_SMEM);

    dim3 tb(32, 8);

    ln_kernel<<<MM, 256>>>(x, ln_g, ln_b, xn);
    pe_kernel<<<(SS*(DD/2) + 255)/256, 256>>>(pe);
    transpose1024<<<dim3(32,32), tb>>>(Wq, wtq);
    transpose1024<<<dim3(32,32), tb>>>(Wk, wtk);
    transpose1024<<<dim3(32,32), tb>>>(Wv, wtv);
    transpose1024<<<dim3(32,32), tb>>>(Wp, wtp);
    transpose1024<<<dim3(32,32), tb>>>(Wo, wto);

    proj_tc<<<dim3(8, 32), 256>>>(xn, wtq, bq, q);
    proj_tc<<<dim3(8, 32), 256>>>(xn, wtk, bk, k);
    proj_tc<<<dim3(8, 32), 256>>>(xn, wtv, bv, v);
    proj_tc<<<dim3(8, 16), 256>>>(pe, wtp, nullptr, p);

    vtrans<<<dim3(64, 2, BB*HH), tb>>>(v, vt);

    flash_tc<<<dim3(16, BB*HH), 256, FLASH_SMEM>>>(q, k, vt, p,
                                                   u_bias, v_bias, head);

    proj_tc<<<dim3(8, 32), 256>>>(head, wto, bo, out);
}

// round 7
// speedup vs baseline: 1.0727x; 1.0727x over previous
#include <cuda_runtime.h>
#include <math.h>
#include <stdint.h>

#define BB 2
#define SS 2048
#define DD 1024
#define HH 16
#define DH 64
#define MM (BB*SS)          // 4096
#define SCALE 0.125f        // dh^-0.5

#define LDQ 68              // tf32 tile row stride (64 cols + pad)
#define LDW 132             // wide row stride (128 cols + pad)

// ------------------------------ scratch ------------------------------------
__device__ float g_xn[MM*DD];
__device__ float g_q [MM*DD];
__device__ float g_k [MM*DD];
__device__ float g_v [MM*DD];
__device__ float g_pe[SS*DD];
__device__ float g_p [SS*DD];
__device__ float g_head[MM*DD];
__device__ float g_wt[5*DD*DD];                   // transposed Wq,Wk,Wv,Wp,Wo
__device__ float g_vt[(size_t)BB*HH*DH*SS];       // per-head transposed V
__device__ float g_B[(size_t)BB*HH*SS*SS];        // B[m,c] = (q_m+v_bias).p_c

// ------------------------------ helpers ------------------------------------
__device__ __forceinline__ uint32_t f2tf(float f) {
    uint32_t u;
    asm("cvt.rna.tf32.f32 %0, %1;" : "=r"(u) : "f"(f));
    return u;
}

__device__ __forceinline__ void mma8(float* c, const uint32_t* a, const uint32_t* b) {
    asm volatile(
        "mma.sync.aligned.m16n8k8.row.col.f32.tf32.tf32.f32 "
        "{%0,%1,%2,%3}, {%4,%5,%6,%7}, {%8,%9}, {%0,%1,%2,%3};"
        : "+f"(c[0]), "+f"(c[1]), "+f"(c[2]), "+f"(c[3])
        : "r"(a[0]), "r"(a[1]), "r"(a[2]), "r"(a[3]), "r"(b[0]), "r"(b[1]));
}

// --------------------- generic nt tf32 GEMM core ---------------------------
template<int BM, int BN>
__device__ __forceinline__ void gemm_nt_core(
    const float* __restrict__ A, int lda,
    const float* __restrict__ Bt, int ldb,
    float* __restrict__ C, int ldc,
    int K,
    const float* __restrict__ abias,
    const float* __restrict__ cbias)
{
    constexpr int WNB = BN / 32;
    __shared__ __align__(16) uint32_t As[BM][36];
    __shared__ __align__(16) uint32_t Bs[BN][36];

    const int t = threadIdx.x;
    const int wid = t >> 5, lane = t & 31;
    const int wm = wid / WNB, wn = wid % WNB;
    const int lr = lane >> 2, lc = lane & 3;

    float acc[4][4][4];
#pragma unroll
    for (int mf = 0; mf < 4; mf++)
#pragma unroll
        for (int nf = 0; nf < 4; nf++)
#pragma unroll
            for (int r = 0; r < 4; r++) acc[mf][nf][r] = 0.f;

    const int arow = t >> 3;
    const int ac4  = (t & 7) << 2;

    for (int k0 = 0; k0 < K; k0 += 32) {
        __syncthreads();
#pragma unroll
        for (int it = 0; it < BM/32; it++) {
            int r = arow + it*32;
            float4 v4 = *(const float4*)(A + (size_t)r*lda + k0 + ac4);
            if (abias) {
                v4.x += abias[k0+ac4+0]; v4.y += abias[k0+ac4+1];
                v4.z += abias[k0+ac4+2]; v4.w += abias[k0+ac4+3];
            }
            uint4 u = make_uint4(f2tf(v4.x), f2tf(v4.y), f2tf(v4.z), f2tf(v4.w));
            *(uint4*)&As[r][ac4] = u;
        }
#pragma unroll
        for (int it = 0; it < BN/32; it++) {
            int r = arow + it*32;
            float4 v4 = *(const float4*)(Bt + (size_t)r*ldb + k0 + ac4);
            uint4 u = make_uint4(f2tf(v4.x), f2tf(v4.y), f2tf(v4.z), f2tf(v4.w));
            *(uint4*)&Bs[r][ac4] = u;
        }
        __syncthreads();

#pragma unroll
        for (int kk = 0; kk < 4; kk++) {
            const int kb = kk * 8;
            uint32_t a[4][4], b[4][2];
#pragma unroll
            for (int mf = 0; mf < 4; mf++) {
                int m = wm*64 + mf*16;
                a[mf][0] = As[m+lr  ][kb+lc  ];
                a[mf][1] = As[m+lr+8][kb+lc  ];
                a[mf][2] = As[m+lr  ][kb+lc+4];
                a[mf][3] = As[m+lr+8][kb+lc+4];
            }
#pragma unroll
            for (int nf = 0; nf < 4; nf++) {
                int n = wn*32 + nf*8;
                b[nf][0] = Bs[n+lr][kb+lc  ];
                b[nf][1] = Bs[n+lr][kb+lc+4];
            }
#pragma unroll
            for (int mf = 0; mf < 4; mf++)
#pragma unroll
                for (int nf = 0; nf < 4; nf++)
                    mma8(acc[mf][nf], a[mf], b[nf]);
        }
    }

#pragma unroll
    for (int mf = 0; mf < 4; mf++) {
        int m = wm*64 + mf*16;
#pragma unroll
        for (int nf = 0; nf < 4; nf++) {
            int n = wn*32 + nf*8 + 2*lc;
            float b0 = cbias ? cbias[n]   : 0.f;
            float b1 = cbias ? cbias[n+1] : 0.f;
            *(float2*)(C + (size_t)(m+lr  )*ldc + n) =
                make_float2(acc[mf][nf][0] + b0, acc[mf][nf][1] + b1);
            *(float2*)(C + (size_t)(m+lr+8)*ldc + n) =
                make_float2(acc[mf][nf][2] + b0, acc[mf][nf][3] + b1);
        }
    }
}

__global__ void __launch_bounds__(256) proj_tc(
    const float* __restrict__ A, const float* __restrict__ Bt,
    const float* __restrict__ cbias, float* __restrict__ C)
{
    const float* Ab  = A  + (size_t)blockIdx.y * 128 * DD;
    const float* Btb = Bt + (size_t)blockIdx.x * 128 * DD;
    float* Cb = C + (size_t)blockIdx.y * 128 * DD + blockIdx.x * 128;
    gemm_nt_core<128,128>(Ab, DD, Btb, DD, Cb, DD, DD, nullptr,
                          cbias ? cbias + blockIdx.x*128 : nullptr);
}

// B GEMM: B[bh, m, c] = (q_m + v_bias_h) . p_c
__global__ void __launch_bounds__(256) score_tc(
    const float* __restrict__ q, const float* __restrict__ key,
    const float* __restrict__ bias, float* __restrict__ out, int key_bstride)
{
    int z = blockIdx.z, b = z >> 4, h = z & 15;
    const float* Ab  = q + (size_t)b*SS*DD + h*DH + (size_t)blockIdx.y * 128 * DD;
    const float* Btb = key + (size_t)b*key_bstride + h*DH + (size_t)blockIdx.x * 128 * DD;
    float* Cb = out + (size_t)z*SS*SS + (size_t)blockIdx.y * 128 * SS + blockIdx.x * 128;
    gemm_nt_core<128,128>(Ab, DD, Btb, DD, Cb, SS, DH, bias + h*DH, nullptr);
}

// =================== fused flash attention (B from DRAM) ====================
// grid (16 i-tiles, 32 bh), 256 threads = 8 warps (warp = 16 query rows).
extern __shared__ char smx[];
#define FLASH2_SMEM ((128*LDQ + 128*LDQ)*4)

__global__ void __launch_bounds__(256, 2) flash2(
    const float* __restrict__ q, const float* __restrict__ kk_,
    const float* __restrict__ vt, const float* __restrict__ Bg,
    const float* __restrict__ u_bias, float* __restrict__ head)
{
    uint32_t* Qu  = (uint32_t*)smx;              // [128][LDQ] tf32, q+u
    uint32_t* Buf = Qu + 128*LDQ;                // K tile [128][LDQ] or Vt tile [64][LDW]

    const int z = blockIdx.y, b = z >> 4, h = z & 15;
    const int i0 = blockIdx.x * 128;
    const int t = threadIdx.x, wid = t >> 5, lane = t & 31;
    const int lr = lane >> 2, lc = lane & 3;
    const int mw = wid * 16;

    const float* qb  = q + (size_t)(b*SS)*DD + h*DH;
    const float* kbp = kk_ + (size_t)(b*SS)*DD + h*DH;
    const float* vtb = vt + (size_t)z*DH*SS;
    const float* Bb  = Bg + (size_t)z*SS*SS;
    const float* ub  = u_bias + h*DH;

    // load Qu = tf32(q + u), 128 rows x 64 cols
    for (int idx = t; idx < 128*16; idx += 256) {
        int row = idx >> 4, c4 = (idx & 15) << 2;
        float4 v4 = *(const float4*)(qb + (size_t)(i0+row)*DD + c4);
        *(uint4*)&Qu[row*LDQ + c4] = make_uint4(
            f2tf(v4.x+ub[c4]), f2tf(v4.y+ub[c4+1]),
            f2tf(v4.z+ub[c4+2]), f2tf(v4.w+ub[c4+3]));
    }

    float sacc[16][4];
    float oacc[8][4];
    float m0 = -1e30f, m1 = -1e30f, l0 = 0.f, l1 = 0.f;
#pragma unroll
    for (int nf = 0; nf < 8; nf++)
#pragma unroll
        for (int c = 0; c < 4; c++) oacc[nf][c] = 0.f;

    for (int j0 = 0; j0 < SS; j0 += 128) {
        __syncthreads();   // Buf free (prev PV done); also orders Qu on first iter

        // ---- K tile ----
        for (int idx = t; idx < 128*16; idx += 256) {
            int row = idx >> 4, c4 = (idx & 15) << 2;
            float4 v4 = *(const float4*)(kbp + (size_t)(j0+row)*DD + c4);
            *(uint4*)&Buf[row*LDQ + c4] = make_uint4(
                f2tf(v4.x), f2tf(v4.y), f2tf(v4.z), f2tf(v4.w));
        }
        __syncthreads();

        // ---- content MMA: sacc = (q+u) . k^T ----
#pragma unroll
        for (int nf = 0; nf < 16; nf++)
#pragma unroll
            for (int c = 0; c < 4; c++) sacc[nf][c] = 0.f;
#pragma unroll
        for (int kk = 0; kk < 8; kk++) {
            int kb8 = kk*8;
            uint32_t a[4];
            a[0] = Qu[(mw+lr  )*LDQ + kb8+lc  ];
            a[1] = Qu[(mw+lr+8)*LDQ + kb8+lc  ];
            a[2] = Qu[(mw+lr  )*LDQ + kb8+lc+4];
            a[3] = Qu[(mw+lr+8)*LDQ + kb8+lc+4];
#pragma unroll
            for (int nf = 0; nf < 16; nf++) {
                uint32_t bb[2];
                bb[0] = Buf[(nf*8+lr)*LDQ + kb8+lc  ];
                bb[1] = Buf[(nf*8+lr)*LDQ + kb8+lc+4];
                mma8(sacc[nf], a, bb);
            }
        }

        // ---- add shifted positional term from B ----
        {
            const int ibase = i0 + mw + lr;
#pragma unroll
            for (int ch = 0; ch < 2; ch++) {
                const int i = ibase + (ch << 3);
                const float* Brow  = Bb + (size_t)i*SS;
                const float* Brow1 = Brow + SS;          // row i+1 (deref guarded)
                const int jb = 2*lc;
#pragma unroll
                for (int nf = 0; nf < 16; nf++) {
#pragma unroll
                    for (int c01 = 0; c01 < 2; c01++) {
                        int j = j0 + nf*8 + jb + c01;
                        float pv;
                        if (j <= i)          pv = __ldg(Brow  + (SS-1-i+j));
                        else if (j == i + 1) pv = 0.f;
                        else                 pv = __ldg(Brow1 + (j-i-2));
                        sacc[nf][ch*2+c01] += pv;
                    }
                }
            }
        }

        // ---- scale + online softmax (probs left in sacc) ----
        float mx0 = -1e30f, mx1 = -1e30f;
#pragma unroll
        for (int nf = 0; nf < 16; nf++) {
            sacc[nf][0] *= SCALE; sacc[nf][1] *= SCALE;
            sacc[nf][2] *= SCALE; sacc[nf][3] *= SCALE;
            mx0 = fmaxf(mx0, fmaxf(sacc[nf][0], sacc[nf][1]));
            mx1 = fmaxf(mx1, fmaxf(sacc[nf][2], sacc[nf][3]));
        }
        mx0 = fmaxf(mx0, __shfl_xor_sync(0xffffffffu, mx0, 1));
        mx0 = fmaxf(mx0, __shfl_xor_sync(0xffffffffu, mx0, 2));
        mx1 = fmaxf(mx1, __shfl_xor_sync(0xffffffffu, mx1, 1));
        mx1 = fmaxf(mx1, __shfl_xor_sync(0xffffffffu, mx1, 2));
        float nm0 = fmaxf(m0, mx0), nm1 = fmaxf(m1, mx1);
        float f0 = __expf(m0 - nm0), f1 = __expf(m1 - nm1);
        float s0 = 0.f, s1 = 0.f;
#pragma unroll
        for (int nf = 0; nf < 16; nf++) {
            sacc[nf][0] = __expf(sacc[nf][0] - nm0);
            sacc[nf][1] = __expf(sacc[nf][1] - nm0);
            sacc[nf][2] = __expf(sacc[nf][2] - nm1);
            sacc[nf][3] = __expf(sacc[nf][3] - nm1);
            s0 += sacc[nf][0] + sacc[nf][1];
            s1 += sacc[nf][2] + sacc[nf][3];
        }
        s0 += __shfl_xor_sync(0xffffffffu, s0, 1);
        s0 += __shfl_xor_sync(0xffffffffu, s0, 2);
        s1 += __shfl_xor_sync(0xffffffffu, s1, 1);
        s1 += __shfl_xor_sync(0xffffffffu, s1, 2);
        l0 = l0*f0 + s0; l1 = l1*f1 + s1;
        m0 = nm0; m1 = nm1;
#pragma unroll
        for (int nf = 0; nf < 8; nf++) {
            oacc[nf][0] *= f0; oacc[nf][1] *= f0;
            oacc[nf][2] *= f1; oacc[nf][3] *= f1;
        }

        // ---- Vt tile (overwrites K region) ----
        __syncthreads();
        for (int idx = t; idx < 64*32; idx += 256) {
            int d = idx >> 5, c4 = (idx & 31) << 2;
            float4 v4 = *(const float4*)(vtb + (size_t)d*SS + j0 + c4);
            *(uint4*)&Buf[d*LDW + c4] = make_uint4(
                f2tf(v4.x), f2tf(v4.y), f2tf(v4.z), f2tf(v4.w));
        }
        __syncthreads();

        // ---- PV MMA: P a-frags via warp shuffles from sacc ----
        const int srcA = lr*4 + (lc>>1);
        const bool odd = lc & 1;
#pragma unroll
        for (int kk = 0; kk < 16; kk++) {
            float p00 = __shfl_sync(0xffffffffu, sacc[kk][0], srcA);
            float p01 = __shfl_sync(0xffffffffu, sacc[kk][1], srcA);
            float p10 = __shfl_sync(0xffffffffu, sacc[kk][2], srcA);
            float p11 = __shfl_sync(0xffffffffu, sacc[kk][3], srcA);
            float r00 = __shfl_sync(0xffffffffu, sacc[kk][0], srcA+2);
            float r01 = __shfl_sync(0xffffffffu, sacc[kk][1], srcA+2);
            float r10 = __shfl_sync(0xffffffffu, sacc[kk][2], srcA+2);
            float r11 = __shfl_sync(0xffffffffu, sacc[kk][3], srcA+2);
            uint32_t a[4];
            a[0] = f2tf(odd ? p01 : p00);
            a[1] = f2tf(odd ? p11 : p10);
            a[2] = f2tf(odd ? r01 : r00);
            a[3] = f2tf(odd ? r11 : r10);
            int kb8 = kk*8;
#pragma unroll
            for (int nf = 0; nf < 8; nf++) {
                uint32_t bb[2];
                bb[0] = Buf[(nf*8+lr)*LDW + kb8+lc  ];
                bb[1] = Buf[(nf*8+lr)*LDW + kb8+lc+4];
                mma8(oacc[nf], a, bb);
            }
        }
    }

    // ---- epilogue ----
    float inv0 = 1.f / l0, inv1 = 1.f / l1;
    float* hb = head + (size_t)(b*SS)*DD + h*DH;
#pragma unroll
    for (int nf = 0; nf < 8; nf++) {
        int n = nf*8 + 2*lc;
        *(float2*)(hb + (size_t)(i0+mw+lr  )*DD + n) =
            make_float2(oacc[nf][0]*inv0, oacc[nf][1]*inv0);
        *(float2*)(hb + (size_t)(i0+mw+lr+8)*DD + n) =
            make_float2(oacc[nf][2]*inv1, oacc[nf][3]*inv1);
    }
}

// ------------------------------ transposes ---------------------------------
__global__ void transpose1024(const float* __restrict__ src, float* __restrict__ dst) {
    __shared__ float tile[32][33];
    int bx = blockIdx.x*32, by = blockIdx.y*32;
    int tx = threadIdx.x, ty = threadIdx.y;
#pragma unroll
    for (int r = 0; r < 32; r += 8)
        tile[ty+r][tx] = src[(size_t)(by+ty+r)*DD + bx+tx];
    __syncthreads();
#pragma unroll
    for (int r = 0; r < 32; r += 8)
        dst[(size_t)(bx+ty+r)*DD + by+tx] = tile[tx][ty+r];
}

__global__ void vtrans(const float* __restrict__ v, float* __restrict__ vt) {
    __shared__ float tile[32][33];
    int z = blockIdx.z, b = z >> 4, h = z & 15;
    int s0 = blockIdx.x*32, d0 = blockIdx.y*32;
    int tx = threadIdx.x, ty = threadIdx.y;
#pragma unroll
    for (int r = 0; r < 32; r += 8)
        tile[ty+r][tx] = v[(size_t)(b*SS + s0+ty+r)*DD + h*DH + d0 + tx];
    __syncthreads();
#pragma unroll
    for (int r = 0; r < 32; r += 8)
        vt[(size_t)z*DH*SS + (size_t)(d0+ty+r)*SS + s0+tx] = tile[tx][ty+r];
}

// ------------------------------ LayerNorm ----------------------------------
__global__ void ln_kernel(const float* __restrict__ x,
                          const float* __restrict__ g,
                          const float* __restrict__ b,
                          float* __restrict__ xn) {
    int row = blockIdx.x;
    const float* xr = x + (size_t)row * DD;
    float* outr = xn + (size_t)row * DD;
    int t = threadIdx.x;

    float s = 0.f, s2 = 0.f;
    for (int i = t; i < DD; i += 256) { float v = xr[i]; s += v; s2 += v*v; }

    __shared__ float rs[256], rs2[256];
    rs[t] = s; rs2[t] = s2; __syncthreads();
    for (int off = 128; off > 0; off >>= 1) {
        if (t < off) { rs[t] += rs[t+off]; rs2[t] += rs2[t+off]; }
        __syncthreads();
    }
    float mean = rs[0] * (1.0f/DD);
    float var  = rs2[0] * (1.0f/DD) - mean*mean;
    float inv  = rsqrtf(var + 1e-5f);
    for (int i = t; i < DD; i += 256)
        outr[i] = (xr[i] - mean) * inv * g[i] + b[i];
}

// ------------------------------ sinusoidal PE -------------------------------
__global__ void pe_kernel(float* __restrict__ pe) {
    int idx = blockIdx.x * blockDim.x + threadIdx.x;
    if (idx >= SS * (DD/2)) return;
    int s = idx / (DD/2);
    int i = idx % (DD/2);
    double div = exp(-(double)(2*i) * log(10000.0) / (double)DD);
    double ang = (double)s * div;
    pe[(size_t)s*DD + 2*i    ] = (float)sin(ang);
    pe[(size_t)s*DD + 2*i + 1] = (float)cos(ang);
}

// ------------------------------ launch -------------------------------------
extern "C" void kernel_launch(void* const* d_in, const int* in_sizes, int n_in,
                              void* d_out, int out_size) {
    const float* x    = (const float*)d_in[0];
    const float* ln_g = (const float*)d_in[1];
    const float* ln_b = (const float*)d_in[2];
    const float* Wq   = (const float*)d_in[3];
    const float* bq   = (const float*)d_in[4];
    const float* Wk   = (const float*)d_in[5];
    const float* bk   = (const float*)d_in[6];
    const float* Wv   = (const float*)d_in[7];
    const float* bv   = (const float*)d_in[8];
    const float* Wp   = (const float*)d_in[9];
    const float* Wo   = (const float*)d_in[10];
    const float* bo   = (const float*)d_in[11];
    const float* u_bias = (const float*)d_in[12];
    const float* v_bias = (const float*)d_in[13];
    float* out = (float*)d_out;

    float *xn, *q, *k, *v, *pe, *p, *head, *wt, *vt, *Bg;
    cudaGetSymbolAddress((void**)&xn, g_xn);
    cudaGetSymbolAddress((void**)&q, g_q);
    cudaGetSymbolAddress((void**)&k, g_k);
    cudaGetSymbolAddress((void**)&v, g_v);
    cudaGetSymbolAddress((void**)&pe, g_pe);
    cudaGetSymbolAddress((void**)&p, g_p);
    cudaGetSymbolAddress((void**)&head, g_head);
    cudaGetSymbolAddress((void**)&wt, g_wt);
    cudaGetSymbolAddress((void**)&vt, g_vt);
    cudaGetSymbolAddress((void**)&Bg, g_B);

    float* wtq = wt + 0*(size_t)DD*DD;
    float* wtk = wt + 1*(size_t)DD*DD;
    float* wtv = wt + 2*(size_t)DD*DD;
    float* wtp = wt + 3*(size_t)DD*DD;
    float* wto = wt + 4*(size_t)DD*DD;

    cudaFuncSetAttribute(flash2, cudaFuncAttributeMaxDynamicSharedMemorySize,
                         FLASH2_SMEM);

    dim3 tb(32, 8);

    ln_kernel<<<MM, 256>>>(x, ln_g, ln_b, xn);
    pe_kernel<<<(SS*(DD/2) + 255)/256, 256>>>(pe);
    transpose1024<<<dim3(32,32), tb>>>(Wq, wtq);
    transpose1024<<<dim3(32,32), tb>>>(Wk, wtk);
    transpose1024<<<dim3(32,32), tb>>>(Wv, wtv);
    transpose1024<<<dim3(32,32), tb>>>(Wp, wtp);
    transpose1024<<<dim3(32,32), tb>>>(Wo, wto);

    proj_tc<<<dim3(8, 32), 256>>>(xn, wtq, bq, q);
    proj_tc<<<dim3(8, 32), 256>>>(xn, wtk, bk, k);
    proj_tc<<<dim3(8, 32), 256>>>(xn, wtv, bv, v);
    proj_tc<<<dim3(8, 16), 256>>>(pe, wtp, nullptr, p);

    vtrans<<<dim3(64, 2, BB*HH), tb>>>(v, vt);

    // B[m,c] = (q_m + v_bias).p_c  (raw positional scores, read shifted by flash2)
    score_tc<<<dim3(16, 16, BB*HH), 256>>>(q, p, v_bias, Bg, 0);

    flash2<<<dim3(16, BB*HH), 256, FLASH2_SMEM>>>(q, k, vt, Bg, u_bias, head);

    proj_tc<<<dim3(8, 32), 256>>>(head, wto, bo, out);
}